// round 3
// baseline (speedup 1.0000x reference)
#include <cuda_runtime.h>
#include <math.h>

// Problem constants
#define LL 1024
#define BB 4
#define DD 1024
#define HH 16
#define HDIM 64
#define DFF_ 4096
#define NROWS 4096        // L*B
#define QKVW 3072         // 3*D

// ---------------- scratch (device globals; no allocation allowed) ------------
__device__ float g_h[(size_t)NROWS * DD];
__device__ float g_qkv[(size_t)NROWS * QKVW];
__device__ float g_attn[(size_t)NROWS * DD];
__device__ float g_x1[(size_t)NROWS * DD];
__device__ float g_h2[(size_t)NROWS * DD];
__device__ float g_ff[(size_t)NROWS * DFF_];

// ---------------- LayerNorm: one block per row, D=1024, 256 threads ----------
__global__ void ln_kernel(const float* __restrict__ X, const float* __restrict__ w,
                          const float* __restrict__ b, float* __restrict__ Y) {
    int row = blockIdx.x;
    int tid = threadIdx.x;
    const float* xr = X + (size_t)row * DD;
    float v0 = xr[tid], v1 = xr[tid + 256], v2 = xr[tid + 512], v3 = xr[tid + 768];
    float s = v0 + v1 + v2 + v3;
    float s2 = v0 * v0 + v1 * v1 + v2 * v2 + v3 * v3;
    #pragma unroll
    for (int off = 16; off; off >>= 1) {
        s  += __shfl_xor_sync(0xffffffffu, s, off);
        s2 += __shfl_xor_sync(0xffffffffu, s2, off);
    }
    __shared__ float sh[16];
    __shared__ float smean, sinv;
    int wid = tid >> 5, lid = tid & 31;
    if (lid == 0) { sh[wid] = s; sh[wid + 8] = s2; }
    __syncthreads();
    if (wid == 0) {
        float a  = (lid < 8) ? sh[lid] : 0.f;
        float a2 = (lid < 8) ? sh[lid + 8] : 0.f;
        #pragma unroll
        for (int off = 4; off; off >>= 1) {
            a  += __shfl_xor_sync(0xffffffffu, a, off, 8);
            a2 += __shfl_xor_sync(0xffffffffu, a2, off, 8);
        }
        if (lid == 0) {
            float mean = a * (1.f / DD);
            float var = a2 * (1.f / DD) - mean * mean;
            smean = mean;
            sinv = rsqrtf(var + 1e-5f);
        }
    }
    __syncthreads();
    float mean = smean, inv = sinv;
    float* yr = Y + (size_t)row * DD;
    yr[tid]       = (v0 - mean) * inv * w[tid]       + b[tid];
    yr[tid + 256] = (v1 - mean) * inv * w[tid + 256] + b[tid + 256];
    yr[tid + 512] = (v2 - mean) * inv * w[tid + 512] + b[tid + 512];
    yr[tid + 768] = (v3 - mean) * inv * w[tid + 768] + b[tid + 768];
}

// ---------------- GEMM: C[M,N] = A[M,K] @ Bw[N,K]^T + bias (+epilogue) -------
// EPI: 0 = bias only, 1 = bias + exact GELU, 2 = bias + residual add
template <int EPI>
__global__ void gemm_tn(const float* __restrict__ A, const float* __restrict__ Bw,
                        const float* __restrict__ bias, const float* __restrict__ Res,
                        float* __restrict__ C, int M, int N, int K) {
    __shared__ float As[32 * 68];
    __shared__ float Bs[32 * 68];
    int m0 = blockIdx.y * 64, n0 = blockIdx.x * 64;
    int tid = threadIdx.x, tx = tid & 15, ty = tid >> 4;
    float acc[4][4] = {};
    for (int k0 = 0; k0 < K; k0 += 32) {
        #pragma unroll
        for (int i = tid; i < 64 * 32; i += 256) {
            int mm = i >> 5, kk = i & 31;
            As[kk * 68 + mm] = A[(size_t)(m0 + mm) * K + k0 + kk];
            Bs[kk * 68 + mm] = Bw[(size_t)(n0 + mm) * K + k0 + kk];
        }
        __syncthreads();
        #pragma unroll 8
        for (int kk = 0; kk < 32; kk++) {
            float4 a = *(const float4*)&As[kk * 68 + ty * 4];
            float4 b = *(const float4*)&Bs[kk * 68 + tx * 4];
            acc[0][0] += a.x * b.x; acc[0][1] += a.x * b.y; acc[0][2] += a.x * b.z; acc[0][3] += a.x * b.w;
            acc[1][0] += a.y * b.x; acc[1][1] += a.y * b.y; acc[1][2] += a.y * b.z; acc[1][3] += a.y * b.w;
            acc[2][0] += a.z * b.x; acc[2][1] += a.z * b.y; acc[2][2] += a.z * b.z; acc[2][3] += a.z * b.w;
            acc[3][0] += a.w * b.x; acc[3][1] += a.w * b.y; acc[3][2] += a.w * b.z; acc[3][3] += a.w * b.w;
        }
        __syncthreads();
    }
    float bj[4];
    #pragma unroll
    for (int j = 0; j < 4; j++) bj[j] = bias[n0 + tx * 4 + j];
    #pragma unroll
    for (int i = 0; i < 4; i++) {
        int m = m0 + ty * 4 + i;
        float out[4];
        #pragma unroll
        for (int j = 0; j < 4; j++) {
            float v = acc[i][j] + bj[j];
            if (EPI == 1) v = 0.5f * v * (1.f + erff(v * 0.70710678118654752f));
            if (EPI == 2) v += Res[(size_t)m * N + n0 + tx * 4 + j];
            out[j] = v;
        }
        *(float4*)&C[(size_t)m * N + n0 + tx * 4] = make_float4(out[0], out[1], out[2], out[3]);
    }
}

// ---------------- Flash attention + edge fusion ------------------------------
// One block per (bh, 64-row q tile). Writes pre-softmax logits t = QK^T/8+edge
// straight to edge_out (== second reference output), online softmax, O = P@V.
__global__ void attn_flash(const float* __restrict__ qkv, const float* __restrict__ edge,
                           float* __restrict__ edge_out, float* __restrict__ attn_out) {
    extern __shared__ float sm[];
    float* Qs = sm;                 // [kk][r]  64x68
    float* Ks = Qs + 64 * 68;       // [kk][c]  64x68
    float* Vs = Ks + 64 * 68;       // [key][d] 64x68
    float* Ps = Vs + 64 * 68;       // [r][kk]  64x68

    int bh = blockIdx.y;
    int q0 = blockIdx.x * 64;
    int b = bh >> 4, hh = bh & 15;
    int tid = threadIdx.x, tx = tid & 15, ty = tid >> 4;

    // load Q tile: Qs[d][r] = qkv[((q0+r)*4+b)*3072 + hh*64 + d]
    for (int i = tid; i < 64 * 64; i += 256) {
        int r = i >> 6, d = i & 63;
        Qs[d * 68 + r] = qkv[((size_t)(q0 + r) * BB + b) * QKVW + hh * HDIM + d];
    }

    float m_run[4], l_run[4], Oacc[4][4];
    #pragma unroll
    for (int i = 0; i < 4; i++) {
        m_run[i] = -1e30f; l_run[i] = 0.f;
        #pragma unroll
        for (int j = 0; j < 4; j++) Oacc[i][j] = 0.f;
    }

    for (int kt = 0; kt < 16; kt++) {
        int k0 = kt * 64;
        __syncthreads();  // protect Ks/Vs from previous iteration's PV gemm
        for (int i = tid; i < 64 * 64; i += 256) {
            int c = i >> 6, d = i & 63;
            size_t base = ((size_t)(k0 + c) * BB + b) * QKVW + hh * HDIM + d;
            Ks[d * 68 + c] = qkv[base + DD];        // K part
            Vs[c * 68 + d] = qkv[base + 2 * DD];    // V part
        }
        __syncthreads();

        // S = Q K^T
        float S[4][4] = {};
        #pragma unroll 8
        for (int kk = 0; kk < 64; kk++) {
            float4 a = *(const float4*)&Qs[kk * 68 + ty * 4];
            float4 bb2 = *(const float4*)&Ks[kk * 68 + tx * 4];
            S[0][0] += a.x * bb2.x; S[0][1] += a.x * bb2.y; S[0][2] += a.x * bb2.z; S[0][3] += a.x * bb2.w;
            S[1][0] += a.y * bb2.x; S[1][1] += a.y * bb2.y; S[1][2] += a.y * bb2.z; S[1][3] += a.y * bb2.w;
            S[2][0] += a.z * bb2.x; S[2][1] += a.z * bb2.y; S[2][2] += a.z * bb2.z; S[2][3] += a.z * bb2.w;
            S[3][0] += a.w * bb2.x; S[3][1] += a.w * bb2.y; S[3][2] += a.w * bb2.z; S[3][3] += a.w * bb2.w;
        }

        // t = S/8 + edge; stream to edge_out; keep t for softmax
        #pragma unroll
        for (int i = 0; i < 4; i++) {
            size_t eoff = (size_t)bh * LL * LL + (size_t)(q0 + ty * 4 + i) * LL + k0 + tx * 4;
            float4 e = *(const float4*)&edge[eoff];
            float t0 = S[i][0] * 0.125f + e.x;
            float t1 = S[i][1] * 0.125f + e.y;
            float t2 = S[i][2] * 0.125f + e.z;
            float t3 = S[i][3] * 0.125f + e.w;
            *(float4*)&edge_out[eoff] = make_float4(t0, t1, t2, t3);
            S[i][0] = t0; S[i][1] = t1; S[i][2] = t2; S[i][3] = t3;
        }

        // online softmax (row reduce across the 16 tx lanes of each half-warp)
        float P[4][4];
        #pragma unroll
        for (int i = 0; i < 4; i++) {
            float rm = fmaxf(fmaxf(S[i][0], S[i][1]), fmaxf(S[i][2], S[i][3]));
            #pragma unroll
            for (int off = 8; off; off >>= 1)
                rm = fmaxf(rm, __shfl_xor_sync(0xffffffffu, rm, off, 16));
            float mn = fmaxf(m_run[i], rm);
            float corr = __expf(m_run[i] - mn);
            float rs = 0.f;
            #pragma unroll
            for (int j = 0; j < 4; j++) { float p = __expf(S[i][j] - mn); P[i][j] = p; rs += p; }
            #pragma unroll
            for (int off = 8; off; off >>= 1)
                rs += __shfl_xor_sync(0xffffffffu, rs, off, 16);
            l_run[i] = l_run[i] * corr + rs;
            m_run[i] = mn;
            #pragma unroll
            for (int j = 0; j < 4; j++) Oacc[i][j] *= corr;
            *(float4*)&Ps[(ty * 4 + i) * 68 + tx * 4] = make_float4(P[i][0], P[i][1], P[i][2], P[i][3]);
        }
        __syncthreads();

        // O += P @ V
        #pragma unroll 8
        for (int kk = 0; kk < 64; kk++) {
            float4 vv = *(const float4*)&Vs[kk * 68 + tx * 4];
            float p0 = Ps[(ty * 4 + 0) * 68 + kk];
            float p1 = Ps[(ty * 4 + 1) * 68 + kk];
            float p2 = Ps[(ty * 4 + 2) * 68 + kk];
            float p3 = Ps[(ty * 4 + 3) * 68 + kk];
            Oacc[0][0] += p0 * vv.x; Oacc[0][1] += p0 * vv.y; Oacc[0][2] += p0 * vv.z; Oacc[0][3] += p0 * vv.w;
            Oacc[1][0] += p1 * vv.x; Oacc[1][1] += p1 * vv.y; Oacc[1][2] += p1 * vv.z; Oacc[1][3] += p1 * vv.w;
            Oacc[2][0] += p2 * vv.x; Oacc[2][1] += p2 * vv.y; Oacc[2][2] += p2 * vv.z; Oacc[2][3] += p2 * vv.w;
            Oacc[3][0] += p3 * vv.x; Oacc[3][1] += p3 * vv.y; Oacc[3][2] += p3 * vv.z; Oacc[3][3] += p3 * vv.w;
        }
    }

    // finalize: write merged layout [l*B+b, D] at column hh*64
    #pragma unroll
    for (int i = 0; i < 4; i++) {
        float inv = 1.f / l_run[i];
        size_t off = ((size_t)(q0 + ty * 4 + i) * BB + b) * DD + hh * HDIM + tx * 4;
        *(float4*)&attn_out[off] =
            make_float4(Oacc[i][0] * inv, Oacc[i][1] * inv, Oacc[i][2] * inv, Oacc[i][3] * inv);
    }
}

// ---------------- host orchestration ----------------------------------------
extern "C" void kernel_launch(void* const* d_in, const int* in_sizes, int n_in,
                              void* d_out, int out_size) {
    const float* x         = (const float*)d_in[0];
    const float* edge      = (const float*)d_in[1];
    const float* in_proj_w = (const float*)d_in[2];
    const float* in_proj_b = (const float*)d_in[3];
    const float* out_proj_w= (const float*)d_in[4];
    const float* out_proj_b= (const float*)d_in[5];
    const float* lin1_w    = (const float*)d_in[6];
    const float* lin1_b    = (const float*)d_in[7];
    const float* lin2_w    = (const float*)d_in[8];
    const float* lin2_b    = (const float*)d_in[9];
    const float* norm1_w   = (const float*)d_in[10];
    const float* norm1_b   = (const float*)d_in[11];
    const float* norm2_w   = (const float*)d_in[12];
    const float* norm2_b   = (const float*)d_in[13];

    float* out_x    = (float*)d_out;
    float* edge_out = (float*)d_out + (size_t)NROWS * DD;

    float *h, *qkv, *attn, *x1, *h2, *ff;
    cudaGetSymbolAddress((void**)&h,    g_h);
    cudaGetSymbolAddress((void**)&qkv,  g_qkv);
    cudaGetSymbolAddress((void**)&attn, g_attn);
    cudaGetSymbolAddress((void**)&x1,   g_x1);
    cudaGetSymbolAddress((void**)&h2,   g_h2);
    cudaGetSymbolAddress((void**)&ff,   g_ff);

    // 1. h = LN1(x)
    ln_kernel<<<NROWS, 256>>>(x, norm1_w, norm1_b, h);

    // 2. qkv = h @ in_proj_w^T + in_proj_b     [4096, 3072]
    gemm_tn<0><<<dim3(QKVW / 64, NROWS / 64), 256>>>(h, in_proj_w, in_proj_b, nullptr, qkv,
                                                     NROWS, QKVW, DD);

    // 3. attention (writes edge_out and merged attn output)
    static int smem_set = 0;
    int smem_bytes = 4 * 64 * 68 * sizeof(float);  // 69632
    if (!smem_set) {
        cudaFuncSetAttribute(attn_flash, cudaFuncAttributeMaxDynamicSharedMemorySize, smem_bytes);
        smem_set = 1;
    }
    attn_flash<<<dim3(16, 64), 256, smem_bytes>>>(qkv, edge, edge_out, attn);

    // 4. x1 = x + attn @ out_proj_w^T + out_proj_b
    gemm_tn<2><<<dim3(DD / 64, NROWS / 64), 256>>>(attn, out_proj_w, out_proj_b, x, x1,
                                                   NROWS, DD, DD);

    // 5. h2 = LN2(x1)
    ln_kernel<<<NROWS, 256>>>(x1, norm2_w, norm2_b, h2);

    // 6. ff = gelu(h2 @ lin1_w^T + lin1_b)     [4096, 4096]
    gemm_tn<1><<<dim3(DFF_ / 64, NROWS / 64), 256>>>(h2, lin1_w, lin1_b, nullptr, ff,
                                                     NROWS, DFF_, DD);

    // 7. out_x = x1 + ff @ lin2_w^T + lin2_b
    gemm_tn<2><<<dim3(DD / 64, NROWS / 64), 256>>>(ff, lin2_w, lin2_b, x1, out_x,
                                                   NROWS, DD, DFF_);
}

// round 6
// speedup vs baseline: 2.9245x; 2.9245x over previous
#include <cuda_runtime.h>
#include <cuda_bf16.h>
#include <math.h>
#include <stdint.h>

// Problem constants
#define LL 1024
#define BB 4
#define DD 1024
#define HH 16
#define HDIM 64
#define DFF_ 4096
#define NROWS 4096        // L*B
#define QKVW 3072         // 3*D

// ---------------- scratch (device globals; no allocation allowed) ------------
__device__ __nv_bfloat16 g_h_hi[(size_t)NROWS * DD],  g_h_lo[(size_t)NROWS * DD];
__device__ float         g_qkv[(size_t)NROWS * QKVW];
__device__ __nv_bfloat16 g_attn_hi[(size_t)NROWS * DD], g_attn_lo[(size_t)NROWS * DD];
__device__ float         g_x1[(size_t)NROWS * DD];
__device__ __nv_bfloat16 g_h2_hi[(size_t)NROWS * DD], g_h2_lo[(size_t)NROWS * DD];
__device__ __nv_bfloat16 g_ff_hi[(size_t)NROWS * DFF_], g_ff_lo[(size_t)NROWS * DFF_];
__device__ __nv_bfloat16 g_w1_hi[(size_t)QKVW * DD], g_w1_lo[(size_t)QKVW * DD];
__device__ __nv_bfloat16 g_w2_hi[(size_t)DD * DD],   g_w2_lo[(size_t)DD * DD];
__device__ __nv_bfloat16 g_w3_hi[(size_t)DFF_ * DD], g_w3_lo[(size_t)DFF_ * DD];
__device__ __nv_bfloat16 g_w4_hi[(size_t)DD * DFF_], g_w4_lo[(size_t)DD * DFF_];

// ---------------- helpers ----------------------------------------------------
__device__ __forceinline__ uint32_t smem_u32(const void* p) {
    uint32_t a;
    asm("{ .reg .u64 t; cvta.to.shared.u64 t, %1; cvt.u32.u64 %0, t; }" : "=r"(a) : "l"(p));
    return a;
}
#define SWZ128(o) ((o) ^ (((o) >> 3) & 0x70))

#define CP16(s, g) asm volatile("cp.async.cg.shared.global [%0], [%1], 16;\n" :: "r"(s), "l"(g) : "memory")
#define CP_COMMIT() asm volatile("cp.async.commit_group;\n" ::: "memory")
#define CP_WAIT1()  asm volatile("cp.async.wait_group 1;\n" ::: "memory")
#define CP_WAIT0()  asm volatile("cp.async.wait_group 0;\n" ::: "memory")

#define LDSM4(r, addr) \
    asm volatile("ldmatrix.sync.aligned.m8n8.x4.shared.b16 {%0,%1,%2,%3}, [%4];" \
        : "=r"((r)[0]), "=r"((r)[1]), "=r"((r)[2]), "=r"((r)[3]) : "r"(addr))

#define MMA16816(d, a, b0, b1) \
    asm volatile("mma.sync.aligned.m16n8k16.row.col.f32.bf16.bf16.f32 " \
        "{%0,%1,%2,%3}, {%4,%5,%6,%7}, {%8,%9}, {%0,%1,%2,%3};" \
        : "+f"((d)[0]), "+f"((d)[1]), "+f"((d)[2]), "+f"((d)[3]) \
        : "r"((a)[0]), "r"((a)[1]), "r"((a)[2]), "r"((a)[3]), "r"(b0), "r"(b1))

__device__ __forceinline__ void split2(float v, __nv_bfloat16& h, __nv_bfloat16& l) {
    h = __float2bfloat16(v);
    l = __float2bfloat16(v - __bfloat162float(h));
}

// ---------------- weight split: fp32 -> bf16 hi/lo ---------------------------
__global__ void split_kernel(const float* __restrict__ src, __nv_bfloat16* __restrict__ hi,
                             __nv_bfloat16* __restrict__ lo, int n) {
    int i = (blockIdx.x * 256 + threadIdx.x) * 4;
    if (i >= n) return;
    float4 v = *(const float4*)(src + i);
    __nv_bfloat16 h0, l0, h1, l1, h2, l2, h3, l3;
    split2(v.x, h0, l0); split2(v.y, h1, l1); split2(v.z, h2, l2); split2(v.w, h3, l3);
    *(__nv_bfloat162*)&hi[i]     = __nv_bfloat162(h0, h1);
    *(__nv_bfloat162*)&hi[i + 2] = __nv_bfloat162(h2, h3);
    *(__nv_bfloat162*)&lo[i]     = __nv_bfloat162(l0, l1);
    *(__nv_bfloat162*)&lo[i + 2] = __nv_bfloat162(l2, l3);
}

// ---------------- LayerNorm -> bf16 hi/lo ------------------------------------
__global__ void ln_split_kernel(const float* __restrict__ X, const float* __restrict__ w,
                                const float* __restrict__ b,
                                __nv_bfloat16* __restrict__ Yhi, __nv_bfloat16* __restrict__ Ylo) {
    int row = blockIdx.x;
    int tid = threadIdx.x;
    const float* xr = X + (size_t)row * DD;
    float v0 = xr[tid], v1 = xr[tid + 256], v2 = xr[tid + 512], v3 = xr[tid + 768];
    float s = v0 + v1 + v2 + v3;
    float s2 = v0 * v0 + v1 * v1 + v2 * v2 + v3 * v3;
    #pragma unroll
    for (int off = 16; off; off >>= 1) {
        s  += __shfl_xor_sync(0xffffffffu, s, off);
        s2 += __shfl_xor_sync(0xffffffffu, s2, off);
    }
    __shared__ float sh[16];
    __shared__ float smean, sinv;
    int wid = tid >> 5, lid = tid & 31;
    if (lid == 0) { sh[wid] = s; sh[wid + 8] = s2; }
    __syncthreads();
    if (wid == 0) {
        float a  = (lid < 8) ? sh[lid] : 0.f;
        float a2 = (lid < 8) ? sh[lid + 8] : 0.f;
        #pragma unroll
        for (int off = 4; off; off >>= 1) {
            a  += __shfl_xor_sync(0xffffffffu, a, off, 8);
            a2 += __shfl_xor_sync(0xffffffffu, a2, off, 8);
        }
        if (lid == 0) {
            float mean = a * (1.f / DD);
            float var = a2 * (1.f / DD) - mean * mean;
            smean = mean;
            sinv = rsqrtf(var + 1e-5f);
        }
    }
    __syncthreads();
    float mean = smean, inv = sinv;
    size_t base = (size_t)row * DD;
    #pragma unroll
    for (int q = 0; q < 4; q++) {
        int c = tid + q * 256;
        float v = (q == 0 ? v0 : q == 1 ? v1 : q == 2 ? v2 : v3);
        float y = (v - mean) * inv * w[c] + b[c];
        __nv_bfloat16 h, l;
        split2(y, h, l);
        Yhi[base + c] = h;
        Ylo[base + c] = l;
    }
}

// ---------------- mma.sync split-bf16 GEMM -----------------------------------
// C[M,N] = (Ahi+Alo)[M,K] @ (Bhi+Blo)[N,K]^T  (3 HMMA passes, fp32 reg accum)
// EPI: 0 = +bias -> OutF ; 1 = gelu(+bias) -> OutHi/OutLo bf16 ; 2 = +bias+Res -> OutF
// CTA 128x128, 8 warps (wm 0..3 = 32-row strip, wn 0..1 = 64-col strip), K-chunk 64.
__global__ void __launch_bounds__(256, 1)
gemm_mma(const __nv_bfloat16* __restrict__ Ahi, const __nv_bfloat16* __restrict__ Alo,
         const __nv_bfloat16* __restrict__ Bhi, const __nv_bfloat16* __restrict__ Blo,
         const float* __restrict__ bias, const float* __restrict__ Res,
         float* __restrict__ OutF, __nv_bfloat16* __restrict__ OutHi,
         __nv_bfloat16* __restrict__ OutLo, int M, int N, int K, int EPI) {
    extern __shared__ __align__(1024) char smem[];
    uint32_t sb = smem_u32(smem);
    int tid = threadIdx.x;
    int w = tid >> 5, lane = tid & 31;
    int wm = w & 3, wn = w >> 2;
    int m0 = blockIdx.y * 128, n0 = blockIdx.x * 128;
    const int nc = K >> 6;

    float acc[2][8][4];
    #pragma unroll
    for (int i = 0; i < 2; i++)
        #pragma unroll
        for (int j = 0; j < 8; j++)
            #pragma unroll
            for (int r = 0; r < 4; r++) acc[i][j][r] = 0.f;

    // ldmatrix per-lane address components
    int rowA = (lane & 7) + (((lane >> 3) & 1) << 3);   // mats: m0-7,m8-15,m0-7,m8-15
    int kbA  = ((lane >> 4) & 1) << 4;                  //       +0B, +0B, +16B, +16B
    int rowB = (lane & 7) + (((lane >> 4) & 1) << 3);   // mats: n0-7,n0-7,n8-15,n8-15
    int kbB  = ((lane >> 3) & 1) << 4;                  //       +0B,+16B, +0B, +16B

    // buffer layout: buf b at sb + b*65536; within: Ahi 0, Alo 16K, Bhi 32K, Blo 48K
    // prologue: load chunk 0 into buf 0
    {
        #pragma unroll
        for (int i = 0; i < 4; i++) {
            int g = tid + (i << 8);
            int row = g >> 3, c = g & 7;
            uint32_t so = SWZ128((uint32_t)(row * 128 + c * 16));
            size_t oa = (size_t)(m0 + row) * K + c * 8;
            size_t ob = (size_t)(n0 + row) * K + c * 8;
            CP16(sb + so,         Ahi + oa);
            CP16(sb + 16384 + so, Alo + oa);
            CP16(sb + 32768 + so, Bhi + ob);
            CP16(sb + 49152 + so, Blo + ob);
        }
        CP_COMMIT();
    }

    for (int kc = 0; kc < nc; kc++) {
        int b = kc & 1;
        if (kc + 1 < nc) {
            if (kc >= 1) __syncthreads();   // all warps done with buf b^1 (iter kc-1)
            int k0 = (kc + 1) << 6;
            uint32_t base = sb + (b ^ 1) * 65536;
            #pragma unroll
            for (int i = 0; i < 4; i++) {
                int g = tid + (i << 8);
                int row = g >> 3, c = g & 7;
                uint32_t so = SWZ128((uint32_t)(row * 128 + c * 16));
                size_t oa = (size_t)(m0 + row) * K + k0 + c * 8;
                size_t ob = (size_t)(n0 + row) * K + k0 + c * 8;
                CP16(base + so,         Ahi + oa);
                CP16(base + 16384 + so, Alo + oa);
                CP16(base + 32768 + so, Bhi + ob);
                CP16(base + 49152 + so, Blo + ob);
            }
            CP_COMMIT();
            CP_WAIT1();     // chunk kc (buf b) resident
        } else {
            CP_WAIT0();
        }
        __syncthreads();

        uint32_t tb = sb + b * 65536;
        #pragma unroll
        for (int ks = 0; ks < 4; ks++) {
            int kb = ks * 32;   // 16 bf16 = 32 bytes per k-step
            uint32_t ah[2][4], al[2][4], bh[4][4], bl[4][4];
            #pragma unroll
            for (int mt = 0; mt < 2; mt++) {
                uint32_t off = SWZ128((uint32_t)((wm * 32 + mt * 16 + rowA) * 128 + kb + kbA));
                LDSM4(ah[mt], tb + off);
                LDSM4(al[mt], tb + 16384 + off);
            }
            #pragma unroll
            for (int p = 0; p < 4; p++) {
                uint32_t off = SWZ128((uint32_t)((wn * 64 + p * 16 + rowB) * 128 + kb + kbB));
                LDSM4(bh[p], tb + 32768 + off);
                LDSM4(bl[p], tb + 49152 + off);
            }
            #pragma unroll
            for (int mt = 0; mt < 2; mt++) {
                #pragma unroll
                for (int nt = 0; nt < 8; nt++) {
                    int p = nt >> 1, h = (nt & 1) * 2;
                    MMA16816(acc[mt][nt], ah[mt], bh[p][h], bh[p][h + 1]);
                    MMA16816(acc[mt][nt], ah[mt], bl[p][h], bl[p][h + 1]);
                    MMA16816(acc[mt][nt], al[mt], bh[p][h], bh[p][h + 1]);
                }
            }
        }
    }

    // epilogue from register accumulators
    int g = lane >> 2, tg = lane & 3;
    #pragma unroll
    for (int mt = 0; mt < 2; mt++) {
        #pragma unroll
        for (int nt = 0; nt < 8; nt++) {
            int r0 = m0 + wm * 32 + mt * 16 + g;
            int c  = n0 + wn * 64 + nt * 8 + tg * 2;
            float b0 = __ldg(&bias[c]), b1 = __ldg(&bias[c + 1]);
            float v00 = acc[mt][nt][0] + b0, v01 = acc[mt][nt][1] + b1;
            float v10 = acc[mt][nt][2] + b0, v11 = acc[mt][nt][3] + b1;
            size_t o0 = (size_t)r0 * N + c;
            size_t o1 = (size_t)(r0 + 8) * N + c;
            if (EPI == 1) {
                v00 = 0.5f * v00 * (1.f + erff(v00 * 0.70710678118654752f));
                v01 = 0.5f * v01 * (1.f + erff(v01 * 0.70710678118654752f));
                v10 = 0.5f * v10 * (1.f + erff(v10 * 0.70710678118654752f));
                v11 = 0.5f * v11 * (1.f + erff(v11 * 0.70710678118654752f));
                __nv_bfloat16 h0, l0, h1, l1;
                split2(v00, h0, l0); split2(v01, h1, l1);
                *(__nv_bfloat162*)&OutHi[o0] = __nv_bfloat162(h0, h1);
                *(__nv_bfloat162*)&OutLo[o0] = __nv_bfloat162(l0, l1);
                split2(v10, h0, l0); split2(v11, h1, l1);
                *(__nv_bfloat162*)&OutHi[o1] = __nv_bfloat162(h0, h1);
                *(__nv_bfloat162*)&OutLo[o1] = __nv_bfloat162(l0, l1);
            } else {
                if (EPI == 2) {
                    float2 r0v = *(const float2*)&Res[o0];
                    float2 r1v = *(const float2*)&Res[o1];
                    v00 += r0v.x; v01 += r0v.y; v10 += r1v.x; v11 += r1v.y;
                }
                *(float2*)&OutF[o0] = make_float2(v00, v01);
                *(float2*)&OutF[o1] = make_float2(v10, v11);
            }
        }
    }
}

// ---------------- Flash attention + edge fusion (fp32) -----------------------
__global__ void attn_flash(const float* __restrict__ qkv, const float* __restrict__ edge,
                           float* __restrict__ edge_out,
                           __nv_bfloat16* __restrict__ attn_hi, __nv_bfloat16* __restrict__ attn_lo) {
    extern __shared__ float sm[];
    float* Qs = sm;                 // [kk][r]  64x68
    float* Ks = Qs + 64 * 68;       // [kk][c]  64x68
    float* Vs = Ks + 64 * 68;       // [key][d] 64x68
    float* Ps = Vs + 64 * 68;       // [r][kk]  64x68

    int bh = blockIdx.y;
    int q0 = blockIdx.x * 64;
    int b = bh >> 4, hh = bh & 15;
    int tid = threadIdx.x, tx = tid & 15, ty = tid >> 4;

    for (int i = tid; i < 64 * 64; i += 256) {
        int r = i >> 6, d = i & 63;
        Qs[d * 68 + r] = qkv[((size_t)(q0 + r) * BB + b) * QKVW + hh * HDIM + d];
    }

    float m_run[4], l_run[4], Oacc[4][4];
    #pragma unroll
    for (int i = 0; i < 4; i++) {
        m_run[i] = -1e30f; l_run[i] = 0.f;
        #pragma unroll
        for (int j = 0; j < 4; j++) Oacc[i][j] = 0.f;
    }

    for (int kt = 0; kt < 16; kt++) {
        int k0 = kt * 64;
        __syncthreads();
        for (int i = tid; i < 64 * 64; i += 256) {
            int c = i >> 6, d = i & 63;
            size_t base = ((size_t)(k0 + c) * BB + b) * QKVW + hh * HDIM + d;
            Ks[d * 68 + c] = qkv[base + DD];
            Vs[c * 68 + d] = qkv[base + 2 * DD];
        }
        __syncthreads();

        float S[4][4] = {};
        #pragma unroll 8
        for (int kk = 0; kk < 64; kk++) {
            float4 a = *(const float4*)&Qs[kk * 68 + ty * 4];
            float4 bb2 = *(const float4*)&Ks[kk * 68 + tx * 4];
            S[0][0] += a.x * bb2.x; S[0][1] += a.x * bb2.y; S[0][2] += a.x * bb2.z; S[0][3] += a.x * bb2.w;
            S[1][0] += a.y * bb2.x; S[1][1] += a.y * bb2.y; S[1][2] += a.y * bb2.z; S[1][3] += a.y * bb2.w;
            S[2][0] += a.z * bb2.x; S[2][1] += a.z * bb2.y; S[2][2] += a.z * bb2.z; S[2][3] += a.z * bb2.w;
            S[3][0] += a.w * bb2.x; S[3][1] += a.w * bb2.y; S[3][2] += a.w * bb2.z; S[3][3] += a.w * bb2.w;
        }

        #pragma unroll
        for (int i = 0; i < 4; i++) {
            size_t eoff = (size_t)bh * LL * LL + (size_t)(q0 + ty * 4 + i) * LL + k0 + tx * 4;
            float4 e = *(const float4*)&edge[eoff];
            float t0 = S[i][0] * 0.125f + e.x;
            float t1 = S[i][1] * 0.125f + e.y;
            float t2 = S[i][2] * 0.125f + e.z;
            float t3 = S[i][3] * 0.125f + e.w;
            *(float4*)&edge_out[eoff] = make_float4(t0, t1, t2, t3);
            S[i][0] = t0; S[i][1] = t1; S[i][2] = t2; S[i][3] = t3;
        }

        float P[4][4];
        #pragma unroll
        for (int i = 0; i < 4; i++) {
            float rm = fmaxf(fmaxf(S[i][0], S[i][1]), fmaxf(S[i][2], S[i][3]));
            #pragma unroll
            for (int off = 8; off; off >>= 1)
                rm = fmaxf(rm, __shfl_xor_sync(0xffffffffu, rm, off, 16));
            float mn = fmaxf(m_run[i], rm);
            float corr = __expf(m_run[i] - mn);
            float rs = 0.f;
            #pragma unroll
            for (int j = 0; j < 4; j++) { float p = __expf(S[i][j] - mn); P[i][j] = p; rs += p; }
            #pragma unroll
            for (int off = 8; off; off >>= 1)
                rs += __shfl_xor_sync(0xffffffffu, rs, off, 16);
            l_run[i] = l_run[i] * corr + rs;
            m_run[i] = mn;
            #pragma unroll
            for (int j = 0; j < 4; j++) Oacc[i][j] *= corr;
            *(float4*)&Ps[(ty * 4 + i) * 68 + tx * 4] = make_float4(P[i][0], P[i][1], P[i][2], P[i][3]);
        }
        __syncthreads();

        #pragma unroll 8
        for (int kk = 0; kk < 64; kk++) {
            float4 vv = *(const float4*)&Vs[kk * 68 + tx * 4];
            float p0 = Ps[(ty * 4 + 0) * 68 + kk];
            float p1 = Ps[(ty * 4 + 1) * 68 + kk];
            float p2 = Ps[(ty * 4 + 2) * 68 + kk];
            float p3 = Ps[(ty * 4 + 3) * 68 + kk];
            Oacc[0][0] += p0 * vv.x; Oacc[0][1] += p0 * vv.y; Oacc[0][2] += p0 * vv.z; Oacc[0][3] += p0 * vv.w;
            Oacc[1][0] += p1 * vv.x; Oacc[1][1] += p1 * vv.y; Oacc[1][2] += p1 * vv.z; Oacc[1][3] += p1 * vv.w;
            Oacc[2][0] += p2 * vv.x; Oacc[2][1] += p2 * vv.y; Oacc[2][2] += p2 * vv.z; Oacc[2][3] += p2 * vv.w;
            Oacc[3][0] += p3 * vv.x; Oacc[3][1] += p3 * vv.y; Oacc[3][2] += p3 * vv.z; Oacc[3][3] += p3 * vv.w;
        }
    }

    // finalize: split to bf16 hi/lo for out_proj A operand
    #pragma unroll
    for (int i = 0; i < 4; i++) {
        float inv = 1.f / l_run[i];
        size_t off = ((size_t)(q0 + ty * 4 + i) * BB + b) * DD + hh * HDIM + tx * 4;
        #pragma unroll
        for (int j = 0; j < 4; j++) {
            float v = Oacc[i][j] * inv;
            __nv_bfloat16 h, l;
            split2(v, h, l);
            attn_hi[off + j] = h;
            attn_lo[off + j] = l;
        }
    }
}

// ---------------- host orchestration ----------------------------------------
extern "C" void kernel_launch(void* const* d_in, const int* in_sizes, int n_in,
                              void* d_out, int out_size) {
    const float* x         = (const float*)d_in[0];
    const float* edge      = (const float*)d_in[1];
    const float* in_proj_w = (const float*)d_in[2];
    const float* in_proj_b = (const float*)d_in[3];
    const float* out_proj_w= (const float*)d_in[4];
    const float* out_proj_b= (const float*)d_in[5];
    const float* lin1_w    = (const float*)d_in[6];
    const float* lin1_b    = (const float*)d_in[7];
    const float* lin2_w    = (const float*)d_in[8];
    const float* lin2_b    = (const float*)d_in[9];
    const float* norm1_w   = (const float*)d_in[10];
    const float* norm1_b   = (const float*)d_in[11];
    const float* norm2_w   = (const float*)d_in[12];
    const float* norm2_b   = (const float*)d_in[13];

    float* out_x    = (float*)d_out;
    float* edge_out = (float*)d_out + (size_t)NROWS * DD;

    __nv_bfloat16 *h_hi, *h_lo, *attn_hi, *attn_lo, *h2_hi, *h2_lo, *ff_hi, *ff_lo;
    __nv_bfloat16 *w1h, *w1l, *w2h, *w2l, *w3h, *w3l, *w4h, *w4l;
    float *qkv, *x1;
    cudaGetSymbolAddress((void**)&h_hi, g_h_hi);   cudaGetSymbolAddress((void**)&h_lo, g_h_lo);
    cudaGetSymbolAddress((void**)&qkv, g_qkv);
    cudaGetSymbolAddress((void**)&attn_hi, g_attn_hi); cudaGetSymbolAddress((void**)&attn_lo, g_attn_lo);
    cudaGetSymbolAddress((void**)&x1, g_x1);
    cudaGetSymbolAddress((void**)&h2_hi, g_h2_hi); cudaGetSymbolAddress((void**)&h2_lo, g_h2_lo);
    cudaGetSymbolAddress((void**)&ff_hi, g_ff_hi); cudaGetSymbolAddress((void**)&ff_lo, g_ff_lo);
    cudaGetSymbolAddress((void**)&w1h, g_w1_hi); cudaGetSymbolAddress((void**)&w1l, g_w1_lo);
    cudaGetSymbolAddress((void**)&w2h, g_w2_hi); cudaGetSymbolAddress((void**)&w2l, g_w2_lo);
    cudaGetSymbolAddress((void**)&w3h, g_w3_hi); cudaGetSymbolAddress((void**)&w3l, g_w3_lo);
    cudaGetSymbolAddress((void**)&w4h, g_w4_hi); cudaGetSymbolAddress((void**)&w4l, g_w4_lo);

    int gemm_smem = 2 * 65536;  // double-buffered 128x64 hi/lo A+B tiles
    cudaFuncSetAttribute(gemm_mma, cudaFuncAttributeMaxDynamicSharedMemorySize, gemm_smem);
    int attn_smem = 4 * 64 * 68 * sizeof(float);  // 69632
    cudaFuncSetAttribute(attn_flash, cudaFuncAttributeMaxDynamicSharedMemorySize, attn_smem);

    // 0. split weights to bf16 hi/lo
    split_kernel<<<(QKVW * DD) / 1024, 256>>>(in_proj_w, w1h, w1l, QKVW * DD);
    split_kernel<<<(DD * DD) / 1024, 256>>>(out_proj_w, w2h, w2l, DD * DD);
    split_kernel<<<(DFF_ * DD) / 1024, 256>>>(lin1_w, w3h, w3l, DFF_ * DD);
    split_kernel<<<(DD * DFF_) / 1024, 256>>>(lin2_w, w4h, w4l, DD * DFF_);

    // 1. h = LN1(x) -> bf16 hi/lo
    ln_split_kernel<<<NROWS, 256>>>(x, norm1_w, norm1_b, h_hi, h_lo);

    // 2. qkv = h @ in_proj_w^T + b   [4096, 3072] fp32 out
    gemm_mma<<<dim3(QKVW / 128, NROWS / 128), 256, gemm_smem>>>(
        h_hi, h_lo, w1h, w1l, in_proj_b, nullptr, qkv, nullptr, nullptr,
        NROWS, QKVW, DD, 0);

    // 3. attention (edge_out + attn hi/lo)
    attn_flash<<<dim3(16, 64), 256, attn_smem>>>(qkv, edge, edge_out, attn_hi, attn_lo);

    // 4. x1 = x + attn @ out_proj_w^T + b   fp32 out
    gemm_mma<<<dim3(DD / 128, NROWS / 128), 256, gemm_smem>>>(
        attn_hi, attn_lo, w2h, w2l, out_proj_b, x, x1, nullptr, nullptr,
        NROWS, DD, DD, 2);

    // 5. h2 = LN2(x1) -> bf16 hi/lo
    ln_split_kernel<<<NROWS, 256>>>(x1, norm2_w, norm2_b, h2_hi, h2_lo);

    // 6. ff = gelu(h2 @ lin1_w^T + b) -> bf16 hi/lo
    gemm_mma<<<dim3(DFF_ / 128, NROWS / 128), 256, gemm_smem>>>(
        h2_hi, h2_lo, w3h, w3l, lin1_b, nullptr, nullptr, ff_hi, ff_lo,
        NROWS, DFF_, DD, 1);

    // 7. out_x = x1 + ff @ lin2_w^T + b
    gemm_mma<<<dim3(DD / 128, NROWS / 128), 256, gemm_smem>>>(
        ff_hi, ff_lo, w4h, w4l, lin2_b, x1, out_x, nullptr, nullptr,
        NROWS, DD, DFF_, 2);
}